// round 13
// baseline (speedup 1.0000x reference)
#include <cuda_runtime.h>
#include <cstdint>

#define NN    50000
#define OBS   15
#define H     64
#define NTHR  256
#define NCTA  444          // 3 CTAs/SM target
#define WS_W  256          // transposed W_hh row stride (floats) — no pad needed

__device__ float    g_social[16 * H];
__device__ float    g_ht[H];        // final target-LSTM hidden state
__device__ unsigned g_cnt;
__device__ unsigned g_tick;
__device__ unsigned g_list[NN];     // packed: idx | (bin << 16)

// ---- activations ------------------------------------------------------------
__device__ __forceinline__ float tanh_ap(float x) {
    float y; asm("tanh.approx.f32 %0, %1;" : "=f"(y) : "f"(x)); return y;
}
__device__ __forceinline__ float sig_ap(float x) { return fmaf(0.5f, tanh_ap(0.5f * x), 0.5f); }
__device__ __forceinline__ float sigf(float x)   { return __fdividef(1.0f, 1.0f + __expf(-x)); }
__device__ __forceinline__ float tanhf_(float x) { return 2.0f * sigf(2.0f * x) - 1.0f; }

// ---------------------------------------------------------------------------
// Filter: keep neighbors with mask[14]!=0 inside the 4x4 window around
// tgt[14] — the only ones whose LSTM output is ever used.
// ---------------------------------------------------------------------------
__global__ void __launch_bounds__(256)
filter_kernel(const float* __restrict__ oth, const int* __restrict__ mask,
              const float* __restrict__ tgt)
{
    int n = blockIdx.x * blockDim.x + threadIdx.x;
    bool valid = false; int bin = 0;
    if (n < NN) {
        float2 xv = ((const float2*)oth)[(size_t)(OBS - 1) * NN + n];
        float rx = xv.x - tgt[(OBS - 1) * 2];
        float ry = xv.y - tgt[(OBS - 1) * 2 + 1];
        int m = mask[(size_t)(OBS - 1) * NN + n];
        bool within = (fabsf(rx) <= 2.0f) && (fabsf(ry) <= 2.0f);
        int cx = (int)truncf(rx) + 2;
        int cy = (int)truncf(ry) + 2;
        valid = within && cx >= 0 && cx < 4 && cy >= 0 && cy < 4 && (m != 0);
        bin = cy * 4 + cx;
    }
    unsigned ball = __ballot_sync(0xffffffffu, valid);
    int lane = threadIdx.x & 31;
    unsigned base = 0;
    if (lane == 0 && ball) base = atomicAdd(&g_cnt, (unsigned)__popc(ball));
    base = __shfl_sync(0xffffffffu, base, 0);
    if (valid) {
        int rank = __popc(ball & ((1u << lane) - 1u));
        g_list[base + rank] = (unsigned)n | ((unsigned)bin << 16);
    }
}

// ---------------------------------------------------------------------------
// Persistent neighbor LSTM, warp-autonomous 4-neighbor tickets (R10 mainloop).
// Gate constants live in smem to cut regs to <=85 so 3 CTAs/SM fit.
// Pooling goes straight to g_social via global atomics (no smem bins).
// Warp 0 of CTA 0 first runs the target LSTM (exact activations, overlapped).
// ---------------------------------------------------------------------------
__global__ void __launch_bounds__(NTHR, 3)
neighbor_kernel(const float* __restrict__ oth,   // (OBS, NN, 2)
                const float* __restrict__ tgt,   // (OBS, 1, 2)
                const float* __restrict__ W_ih,  // (256, 2)
                const float* __restrict__ b_ih,  // (256)
                const float* __restrict__ W_hh,  // (256, 64)
                const float* __restrict__ b_hh)  // (256)
{
    extern __shared__ float sm[];
    float* Ws  = sm;                  // [64][WS_W]  Ws[k][j] = W_hh[j][k]
    float* hsA = Ws + H * WS_W;       // [8][64][4] per-warp h, layout [j][i]
    float* cs  = hsA + 8 * H * 4;     // [3][256]: bb | wx0 | wx1 (slot g*32+lane)

    const int tid  = threadIdx.x;
    const int lane = tid & 31;
    const int wid  = tid >> 5;
    float* hw = hsA + wid * (H * 4);

    const unsigned cnt = g_cnt;
    const unsigned ntk = (cnt + 3u) >> 2;

    // Late-wave fast exit (before staging anything). CTA 0 must stay: target LSTM.
    if (blockIdx.x != 0 && *(volatile unsigned*)&g_tick >= ntk) return;

    // stage W_hh transposed (once per CTA)
    for (int idx = tid; idx < 4 * H * H; idx += NTHR) {
        int j = idx >> 6, k = idx & 63;
        Ws[k * WS_W + j] = W_hh[idx];
    }
    // gate constants: slot g=2q+u at [g*32+lane] -> row j = 64q + 2*lane + u
    {
        int gg = tid >> 5, ll = tid & 31;
        int j = 64 * (gg >> 1) + 2 * ll + (gg & 1);
        cs[tid]       = b_ih[j] + b_hh[j];
        cs[256 + tid] = W_ih[2 * j];
        cs[512 + tid] = W_ih[2 * j + 1];
    }
    __syncthreads();   // Ws + cs ready

    // ---- target LSTM: warp 0 of CTA 0, overlapped with ticket work --------
    if (blockIdx.x == 0 && wid == 0) {
        float bbT[8], wT0[8], wT1[8];
        #pragma unroll
        for (int q = 0; q < 4; q++)
            #pragma unroll
            for (int u = 0; u < 2; u++) {
                int j = 64 * q + lane + 32 * u;
                bbT[2 * q + u] = b_ih[j] + b_hh[j];
                wT0[2 * q + u] = W_ih[2 * j];
                wT1[2 * q + u] = W_ih[2 * j + 1];
            }
        float h0 = 0.f, h1 = 0.f, c0 = 0.f, c1 = 0.f;
        for (int t = 0; t < OBS; t++) {
            float x0 = tgt[2 * t], x1 = tgt[2 * t + 1];
            float a[8];
            #pragma unroll
            for (int g = 0; g < 8; g++)
                a[g] = fmaf(wT1[g], x1, fmaf(wT0[g], x0, bbT[g]));
            #pragma unroll 4
            for (int k = 0; k < 32; k++) {
                float hk0 = __shfl_sync(0xffffffffu, h0, k);
                float hk1 = __shfl_sync(0xffffffffu, h1, k);
                #pragma unroll
                for (int g = 0; g < 8; g++) {
                    int j = 64 * (g >> 1) + lane + 32 * (g & 1);
                    a[g] = fmaf(Ws[k * WS_W + j], hk0, a[g]);
                    a[g] = fmaf(Ws[(k + 32) * WS_W + j], hk1, a[g]);
                }
            }
            float i0 = sigf(a[0]), f0 = sigf(a[2]), g0 = tanhf_(a[4]), o0 = sigf(a[6]);
            float i1 = sigf(a[1]), f1 = sigf(a[3]), g1 = tanhf_(a[5]), o1 = sigf(a[7]);
            c0 = fmaf(f0, c0, i0 * g0);  h0 = o0 * tanhf_(c0);
            c1 = fmaf(f1, c1, i1 * g1);  h1 = o1 * tanhf_(c1);
        }
        g_ht[lane]      = h0;
        g_ht[lane + 32] = h1;
    }

    while (true) {
        unsigned tk = 0;
        if (lane == 0) tk = atomicAdd(&g_tick, 1u);
        tk = __shfl_sync(0xffffffffu, tk, 0);
        const unsigned base = tk * 4;
        if (base >= cnt) break;          // warp-uniform

        // slots + x(0): lanes 0..3 own one neighbor each
        unsigned pk = 0xffffffffu;
        float2 xv = make_float2(0.0f, 0.0f);
        if (lane < 4 && base + lane < cnt) {
            pk = g_list[base + lane];
            xv = ((const float2*)oth)[pk & 0xffffu];
        }

        // zero this warp's h rows (2*lane, 2*lane+1)
        *(float4*)(hw + (2 * lane)     * 4) = make_float4(0.f, 0.f, 0.f, 0.f);
        *(float4*)(hw + (2 * lane + 1) * 4) = make_float4(0.f, 0.f, 0.f, 0.f);

        float creg[4][2];
        #pragma unroll
        for (int i = 0; i < 4; i++) { creg[i][0] = 0.0f; creg[i][1] = 0.0f; }

        #pragma unroll 1
        for (int t = 0; t < OBS; t++) {
            __syncwarp();   // h(t-1) writes visible

            float xi0[4], xi1[4];
            #pragma unroll
            for (int i = 0; i < 4; i++) {
                xi0[i] = __shfl_sync(0xffffffffu, xv.x, i);
                xi1[i] = __shfl_sync(0xffffffffu, xv.y, i);
            }
            // prefetch x(t+1)
            float2 xn = make_float2(0.0f, 0.0f);
            if (lane < 4 && t + 1 < OBS && pk != 0xffffffffu)
                xn = ((const float2*)oth)[(size_t)(t + 1) * NN + (pk & 0xffffu)];

            float acc[4][8];
            #pragma unroll
            for (int g = 0; g < 8; g++) {
                float bbg = cs[g * 32 + lane];
                float w0g = cs[256 + g * 32 + lane];
                float w1g = cs[512 + g * 32 + lane];
                #pragma unroll
                for (int i = 0; i < 4; i++)
                    acc[i][g] = fmaf(w1g, xi1[i], fmaf(w0g, xi0[i], bbg));
            }

            const float* wcol = Ws + 2 * lane;
            #pragma unroll 8
            for (int k = 0; k < H; k++) {
                float4 h4 = *(const float4*)(hw + k * 4);   // warp-broadcast
                float2 w0 = *(const float2*)(wcol + k * WS_W);
                float2 w1 = *(const float2*)(wcol + k * WS_W + 64);
                float2 w2 = *(const float2*)(wcol + k * WS_W + 128);
                float2 w3 = *(const float2*)(wcol + k * WS_W + 192);
                float hh[4] = {h4.x, h4.y, h4.z, h4.w};
                #pragma unroll
                for (int i = 0; i < 4; i++) {
                    acc[i][0] = fmaf(w0.x, hh[i], acc[i][0]);
                    acc[i][1] = fmaf(w0.y, hh[i], acc[i][1]);
                    acc[i][2] = fmaf(w1.x, hh[i], acc[i][2]);
                    acc[i][3] = fmaf(w1.y, hh[i], acc[i][3]);
                    acc[i][4] = fmaf(w2.x, hh[i], acc[i][4]);
                    acc[i][5] = fmaf(w2.y, hh[i], acc[i][5]);
                    acc[i][6] = fmaf(w3.x, hh[i], acc[i][6]);
                    acc[i][7] = fmaf(w3.y, hh[i], acc[i][7]);
                }
            }
            __syncwarp();   // all h reads done before overwrite

            float hnew[4][2];
            #pragma unroll
            for (int i = 0; i < 4; i++)
                #pragma unroll
                for (int u = 0; u < 2; u++) {
                    float ig = sig_ap (acc[i][0 + u]);
                    float fg = sig_ap (acc[i][2 + u]);
                    float gg = tanh_ap(acc[i][4 + u]);
                    float og = sig_ap (acc[i][6 + u]);
                    float c  = fmaf(fg, creg[i][u], ig * gg);
                    creg[i][u] = c;
                    hnew[i][u] = og * tanh_ap(c);
                }
            #pragma unroll
            for (int u = 0; u < 2; u++) {
                float4 v = {hnew[0][u], hnew[1][u], hnew[2][u], hnew[3][u]};
                *(float4*)(hw + (2 * lane + u) * 4) = v;
            }
            xv = xn;
        }
        __syncwarp();

        // pooling: straight to g_social (spread addresses; lane j and j+32)
        #pragma unroll
        for (int i = 0; i < 4; i++) {
            unsigned pki = __shfl_sync(0xffffffffu, pk, i);
            if (pki != 0xffffffffu) {
                int bin = (int)(pki >> 16);
                atomicAdd(&g_social[bin * H + lane],      hw[lane * 4 + i]);
                atomicAdd(&g_social[bin * H + lane + 32], hw[(lane + 32) * 4 + i]);
            }
        }
    }
}

// ---------------------------------------------------------------------------
// MLP epilogue: ctx = relu(s1 @ W1^T + b1) @ W2^T + b2; out = Wc(h_t+ctx)+bc.
// ---------------------------------------------------------------------------
__global__ void __launch_bounds__(256)
mlp_kernel(const float* __restrict__ W1, const float* __restrict__ b1,
           const float* __restrict__ W2, const float* __restrict__ b2,
           const float* __restrict__ Wc, const float* __restrict__ bc,
           float* __restrict__ out)
{
    __shared__ float s1[16 * H], hid[H], comb[H];
    const int tid  = threadIdx.x;
    const int lane = tid & 31;
    const int wid  = tid >> 5;

    for (int i = tid; i < 16 * H; i += 256) s1[i] = g_social[i];
    __syncthreads();

    #pragma unroll
    for (int rr = 0; rr < 8; rr++) {
        int r = wid * 8 + rr;
        float p = 0.f;
        #pragma unroll 8
        for (int i = 0; i < 32; i++)
            p = fmaf(W1[r * 1024 + i * 32 + lane], s1[i * 32 + lane], p);
        #pragma unroll
        for (int off = 16; off; off >>= 1) p += __shfl_xor_sync(0xffffffffu, p, off);
        if (lane == 0) hid[r] = fmaxf(p + b1[r], 0.0f);
    }
    __syncthreads();

    #pragma unroll
    for (int rr = 0; rr < 8; rr++) {
        int r = wid * 8 + rr;
        float p = 0.f;
        #pragma unroll
        for (int i = 0; i < 2; i++)
            p = fmaf(W2[r * 64 + i * 32 + lane], hid[i * 32 + lane], p);
        #pragma unroll
        for (int off = 16; off; off >>= 1) p += __shfl_xor_sync(0xffffffffu, p, off);
        if (lane == 0) comb[r] = g_ht[r] + p + b2[r];
    }
    __syncthreads();

    if (wid < 2) {
        float p = 0.f;
        #pragma unroll
        for (int i = 0; i < 2; i++)
            p = fmaf(Wc[wid * 64 + i * 32 + lane], comb[i * 32 + lane], p);
        #pragma unroll
        for (int off = 16; off; off >>= 1) p += __shfl_xor_sync(0xffffffffu, p, off);
        if (lane == 0) out[wid] = p + bc[wid];
    }
}

// ---------------------------------------------------------------------------
extern "C" void kernel_launch(void* const* d_in, const int* in_sizes, int n_in,
                              void* d_out, int out_size)
{
    const float* tgt  = (const float*)d_in[0];
    const float* oth  = (const float*)d_in[1];
    const int*   mask = (const int*)  d_in[2];
    const float* W_ih = (const float*)d_in[3];
    const float* b_ih = (const float*)d_in[4];
    const float* W_hh = (const float*)d_in[5];
    const float* b_hh = (const float*)d_in[6];
    const float* W1   = (const float*)d_in[7];
    const float* b1   = (const float*)d_in[8];
    const float* W2   = (const float*)d_in[9];
    const float* b2   = (const float*)d_in[10];
    const float* Wc   = (const float*)d_in[11];
    const float* bc   = (const float*)d_in[12];

    void* p;
    cudaGetSymbolAddress(&p, g_social); cudaMemsetAsync(p, 0, 16 * H * sizeof(float));
    cudaGetSymbolAddress(&p, g_cnt);    cudaMemsetAsync(p, 0, sizeof(unsigned));
    cudaGetSymbolAddress(&p, g_tick);   cudaMemsetAsync(p, 0, sizeof(unsigned));

    const int smemN = (H * WS_W + 8 * H * 4 + 3 * 256) * 4;   // 76800 B
    cudaFuncSetAttribute((const void*)neighbor_kernel,
                         cudaFuncAttributeMaxDynamicSharedMemorySize, smemN);

    filter_kernel<<<(NN + 255) / 256, 256>>>(oth, mask, tgt);
    neighbor_kernel<<<NCTA, NTHR, smemN>>>(oth, tgt, W_ih, b_ih, W_hh, b_hh);
    mlp_kernel<<<1, 256>>>(W1, b1, W2, b2, Wc, bc, (float*)d_out);
}

// round 16
// speedup vs baseline: 1.1058x; 1.1058x over previous
#include <cuda_runtime.h>
#include <cstdint>

#define NN    50000
#define OBS   15
#define H     64
#define NTHR  256
#define NCTA  296          // exactly 2 CTAs/SM — all co-resident (grid barrier safe)
#define WP    260          // transposed W_hh row stride (floats)

__device__ float    g_social[16 * H];
__device__ float    g_ht[H];        // final target-LSTM hidden state
__device__ unsigned g_cnt;
__device__ unsigned g_tick;
__device__ unsigned g_fdone;
__device__ unsigned g_list[NN];     // packed: idx | (bin << 16)

// ---- activations ------------------------------------------------------------
__device__ __forceinline__ float tanh_ap(float x) {
    float y; asm("tanh.approx.f32 %0, %1;" : "=f"(y) : "f"(x)); return y;
}
__device__ __forceinline__ float sig_ap(float x) { return fmaf(0.5f, tanh_ap(0.5f * x), 0.5f); }
__device__ __forceinline__ float sigf(float x)   { return __fdividef(1.0f, 1.0f + __expf(-x)); }
__device__ __forceinline__ float tanhf_(float x) { return 2.0f * sigf(2.0f * x) - 1.0f; }

// ---------------------------------------------------------------------------
// Persistent kernel: integrated filter (block-uniform loop + grid barrier) +
// warp-autonomous 4-neighbor LSTM tickets (R10 mainloop) + social pooling.
// __launch_bounds__(NTHR, 2) guarantees regs <= 128 so 2 CTAs/SM is a
// compile-time certainty -> the 296-CTA grid is fully co-resident and the
// spin barrier cannot deadlock.
// ---------------------------------------------------------------------------
__global__ void __launch_bounds__(NTHR, 2)
neighbor_kernel(const float* __restrict__ oth,   // (OBS, NN, 2)
                const int*   __restrict__ mask,  // (OBS, NN)
                const float* __restrict__ tgt,   // (OBS, 1, 2)
                const float* __restrict__ W_ih,  // (256, 2)
                const float* __restrict__ b_ih,  // (256)
                const float* __restrict__ W_hh,  // (256, 64)
                const float* __restrict__ b_hh)  // (256)
{
    extern __shared__ float sm[];
    float* Ws   = sm;                 // [64][WP]  Ws[k][j] = W_hh[j][k]
    float* hsA  = Ws + H * WP;        // [8][64][4] per-warp h, layout [j][i]
    float* bins = hsA + 8 * H * 4;    // [16*64]

    const int tid  = threadIdx.x;
    const int lane = tid & 31;
    const int wid  = tid >> 5;
    float* hw = hsA + wid * (H * 4);

    // ---- phase 0: filter this CTA's slice (block-uniform trip count) ------
    {
        const float rfx = tgt[(OBS - 1) * 2];
        const float rfy = tgt[(OBS - 1) * 2 + 1];
        const int per = (NN + NCTA - 1) / NCTA;      // 169
        const int lo  = blockIdx.x * per;
        const int hi  = min(lo + per, NN);
        for (int nb = lo; nb < hi; nb += NTHR) {     // same trips for ALL threads
            const int n = nb + tid;
            bool valid = false; int bin = 0;
            if (n < hi) {
                float2 xv = ((const float2*)oth)[(size_t)(OBS - 1) * NN + n];
                float rx = xv.x - rfx;
                float ry = xv.y - rfy;
                int m = mask[(size_t)(OBS - 1) * NN + n];
                bool within = (fabsf(rx) <= 2.0f) && (fabsf(ry) <= 2.0f);
                int cx = (int)truncf(rx) + 2;
                int cy = (int)truncf(ry) + 2;
                valid = within && cx >= 0 && cx < 4 && cy >= 0 && cy < 4 && (m != 0);
                bin = cy * 4 + cx;
            }
            unsigned ball = __ballot_sync(0xffffffffu, valid);
            unsigned base = 0;
            if (lane == 0 && ball) base = atomicAdd(&g_cnt, (unsigned)__popc(ball));
            base = __shfl_sync(0xffffffffu, base, 0);
            if (valid) {
                int rank = __popc(ball & ((1u << lane) - 1u));
                g_list[base + rank] = (unsigned)n | ((unsigned)bin << 16);
            }
        }
    }

    // stage W_hh transposed + bins while other CTAs finish filtering
    for (int idx = tid; idx < 4 * H * H; idx += NTHR) {
        int j = idx >> 6, k = idx & 63;
        Ws[k * WP + j] = W_hh[idx];
    }
    for (int i = tid; i < 16 * H; i += NTHR) bins[i] = 0.0f;

    // per-thread gate-row constants: slot g=2q+u -> row j = 64q + 2*lane + u
    float wx0[8], wx1[8], bb[8];
    #pragma unroll
    for (int q = 0; q < 4; q++)
        #pragma unroll
        for (int u = 0; u < 2; u++) {
            int j = 64 * q + 2 * lane + u;
            wx0[q * 2 + u] = W_ih[2 * j];
            wx1[q * 2 + u] = W_ih[2 * j + 1];
            bb [q * 2 + u] = b_ih[j] + b_hh[j];
        }

    // ---- grid barrier: all 296 CTAs co-resident by construction -----------
    __threadfence();
    __syncthreads();
    if (tid == 0) {
        atomicAdd(&g_fdone, 1u);
        while (*(volatile unsigned*)&g_fdone < NCTA) { }
    }
    __syncthreads();   // list + cnt complete and visible

    // ---- target LSTM: warp 0 of CTA 0, overlapped with ticket work --------
    if (blockIdx.x == 0 && wid == 0) {
        float bbT[8], wT0[8], wT1[8];
        #pragma unroll
        for (int q = 0; q < 4; q++)
            #pragma unroll
            for (int u = 0; u < 2; u++) {
                int j = 64 * q + lane + 32 * u;
                bbT[2 * q + u] = b_ih[j] + b_hh[j];
                wT0[2 * q + u] = W_ih[2 * j];
                wT1[2 * q + u] = W_ih[2 * j + 1];
            }
        float h0 = 0.f, h1 = 0.f, c0 = 0.f, c1 = 0.f;
        for (int t = 0; t < OBS; t++) {
            float x0 = tgt[2 * t], x1 = tgt[2 * t + 1];
            float a[8];
            #pragma unroll
            for (int g = 0; g < 8; g++)
                a[g] = fmaf(wT1[g], x1, fmaf(wT0[g], x0, bbT[g]));
            #pragma unroll 4
            for (int k = 0; k < 32; k++) {
                float hk0 = __shfl_sync(0xffffffffu, h0, k);
                float hk1 = __shfl_sync(0xffffffffu, h1, k);
                #pragma unroll
                for (int g = 0; g < 8; g++) {
                    int j = 64 * (g >> 1) + lane + 32 * (g & 1);
                    a[g] = fmaf(Ws[k * WP + j], hk0, a[g]);
                    a[g] = fmaf(Ws[(k + 32) * WP + j], hk1, a[g]);
                }
            }
            float i0 = sigf(a[0]), f0 = sigf(a[2]), g0 = tanhf_(a[4]), o0 = sigf(a[6]);
            float i1 = sigf(a[1]), f1 = sigf(a[3]), g1 = tanhf_(a[5]), o1 = sigf(a[7]);
            c0 = fmaf(f0, c0, i0 * g0);  h0 = o0 * tanhf_(c0);
            c1 = fmaf(f1, c1, i1 * g1);  h1 = o1 * tanhf_(c1);
        }
        g_ht[lane]      = h0;
        g_ht[lane + 32] = h1;
    }

    const unsigned cnt = *(volatile unsigned*)&g_cnt;

    while (true) {
        unsigned tk = 0;
        if (lane == 0) tk = atomicAdd(&g_tick, 1u);
        tk = __shfl_sync(0xffffffffu, tk, 0);
        const unsigned base = tk * 4;
        if (base >= cnt) break;          // warp-uniform

        // slots + x(0): lanes 0..3 own one neighbor each
        unsigned pk = 0xffffffffu;
        float2 xv = make_float2(0.0f, 0.0f);
        if (lane < 4 && base + lane < cnt) {
            pk = __ldcg(&g_list[base + lane]);
            xv = ((const float2*)oth)[pk & 0xffffu];
        }

        // zero this warp's h rows (2*lane, 2*lane+1)
        *(float4*)(hw + (2 * lane)     * 4) = make_float4(0.f, 0.f, 0.f, 0.f);
        *(float4*)(hw + (2 * lane + 1) * 4) = make_float4(0.f, 0.f, 0.f, 0.f);

        float creg[4][2];
        #pragma unroll
        for (int i = 0; i < 4; i++) { creg[i][0] = 0.0f; creg[i][1] = 0.0f; }

        #pragma unroll 1
        for (int t = 0; t < OBS; t++) {
            __syncwarp();   // h(t-1) writes visible

            float xi0[4], xi1[4];
            #pragma unroll
            for (int i = 0; i < 4; i++) {
                xi0[i] = __shfl_sync(0xffffffffu, xv.x, i);
                xi1[i] = __shfl_sync(0xffffffffu, xv.y, i);
            }
            // prefetch x(t+1)
            float2 xn = make_float2(0.0f, 0.0f);
            if (lane < 4 && t + 1 < OBS && pk != 0xffffffffu)
                xn = ((const float2*)oth)[(size_t)(t + 1) * NN + (pk & 0xffffu)];

            float acc[4][8];
            #pragma unroll
            for (int i = 0; i < 4; i++)
                #pragma unroll
                for (int g = 0; g < 8; g++)
                    acc[i][g] = fmaf(wx1[g], xi1[i], fmaf(wx0[g], xi0[i], bb[g]));

            const float* wcol = Ws + 2 * lane;
            #pragma unroll 8
            for (int k = 0; k < H; k++) {
                float4 h4 = *(const float4*)(hw + k * 4);   // warp-broadcast
                float2 w0 = *(const float2*)(wcol + k * WP);
                float2 w1 = *(const float2*)(wcol + k * WP + 64);
                float2 w2 = *(const float2*)(wcol + k * WP + 128);
                float2 w3 = *(const float2*)(wcol + k * WP + 192);
                float hh[4] = {h4.x, h4.y, h4.z, h4.w};
                #pragma unroll
                for (int i = 0; i < 4; i++) {
                    acc[i][0] = fmaf(w0.x, hh[i], acc[i][0]);
                    acc[i][1] = fmaf(w0.y, hh[i], acc[i][1]);
                    acc[i][2] = fmaf(w1.x, hh[i], acc[i][2]);
                    acc[i][3] = fmaf(w1.y, hh[i], acc[i][3]);
                    acc[i][4] = fmaf(w2.x, hh[i], acc[i][4]);
                    acc[i][5] = fmaf(w2.y, hh[i], acc[i][5]);
                    acc[i][6] = fmaf(w3.x, hh[i], acc[i][6]);
                    acc[i][7] = fmaf(w3.y, hh[i], acc[i][7]);
                }
            }
            __syncwarp();   // all h reads done before overwrite

            float hnew[4][2];
            #pragma unroll
            for (int i = 0; i < 4; i++)
                #pragma unroll
                for (int u = 0; u < 2; u++) {
                    float ig = sig_ap (acc[i][0 + u]);
                    float fg = sig_ap (acc[i][2 + u]);
                    float gg = tanh_ap(acc[i][4 + u]);
                    float og = sig_ap (acc[i][6 + u]);
                    float c  = fmaf(fg, creg[i][u], ig * gg);
                    creg[i][u] = c;
                    hnew[i][u] = og * tanh_ap(c);
                }
            #pragma unroll
            for (int u = 0; u < 2; u++) {
                float4 v = {hnew[0][u], hnew[1][u], hnew[2][u], hnew[3][u]};
                *(float4*)(hw + (2 * lane + u) * 4) = v;
            }
            xv = xn;
        }
        __syncwarp();

        // pooling: lane handles j = lane and j = lane+32 for the 4 neighbors
        #pragma unroll
        for (int i = 0; i < 4; i++) {
            unsigned pki = __shfl_sync(0xffffffffu, pk, i);
            if (pki != 0xffffffffu) {
                int bin = (int)(pki >> 16);
                atomicAdd(&bins[bin * H + lane],      hw[lane * 4 + i]);
                atomicAdd(&bins[bin * H + lane + 32], hw[(lane + 32) * 4 + i]);
            }
        }
    }
    __syncthreads();
    for (int i = tid; i < 16 * H; i += NTHR)
        atomicAdd(&g_social[i], bins[i]);
}

// ---------------------------------------------------------------------------
// MLP epilogue: ctx = relu(s1 @ W1^T + b1) @ W2^T + b2; out = Wc(h_t+ctx)+bc.
// ---------------------------------------------------------------------------
__global__ void __launch_bounds__(256)
mlp_kernel(const float* __restrict__ W1, const float* __restrict__ b1,
           const float* __restrict__ W2, const float* __restrict__ b2,
           const float* __restrict__ Wc, const float* __restrict__ bc,
           float* __restrict__ out)
{
    __shared__ float s1[16 * H], hid[H], comb[H];
    const int tid  = threadIdx.x;
    const int lane = tid & 31;
    const int wid  = tid >> 5;

    for (int i = tid; i < 16 * H; i += 256) s1[i] = g_social[i];
    __syncthreads();

    #pragma unroll
    for (int rr = 0; rr < 8; rr++) {
        int r = wid * 8 + rr;
        float p = 0.f;
        #pragma unroll 8
        for (int i = 0; i < 32; i++)
            p = fmaf(W1[r * 1024 + i * 32 + lane], s1[i * 32 + lane], p);
        #pragma unroll
        for (int off = 16; off; off >>= 1) p += __shfl_xor_sync(0xffffffffu, p, off);
        if (lane == 0) hid[r] = fmaxf(p + b1[r], 0.0f);
    }
    __syncthreads();

    #pragma unroll
    for (int rr = 0; rr < 8; rr++) {
        int r = wid * 8 + rr;
        float p = 0.f;
        #pragma unroll
        for (int i = 0; i < 2; i++)
            p = fmaf(W2[r * 64 + i * 32 + lane], hid[i * 32 + lane], p);
        #pragma unroll
        for (int off = 16; off; off >>= 1) p += __shfl_xor_sync(0xffffffffu, p, off);
        if (lane == 0) comb[r] = g_ht[r] + p + b2[r];
    }
    __syncthreads();

    if (wid < 2) {
        float p = 0.f;
        #pragma unroll
        for (int i = 0; i < 2; i++)
            p = fmaf(Wc[wid * 64 + i * 32 + lane], comb[i * 32 + lane], p);
        #pragma unroll
        for (int off = 16; off; off >>= 1) p += __shfl_xor_sync(0xffffffffu, p, off);
        if (lane == 0) out[wid] = p + bc[wid];
    }
}

// ---------------------------------------------------------------------------
extern "C" void kernel_launch(void* const* d_in, const int* in_sizes, int n_in,
                              void* d_out, int out_size)
{
    const float* tgt  = (const float*)d_in[0];
    const float* oth  = (const float*)d_in[1];
    const int*   mask = (const int*)  d_in[2];
    const float* W_ih = (const float*)d_in[3];
    const float* b_ih = (const float*)d_in[4];
    const float* W_hh = (const float*)d_in[5];
    const float* b_hh = (const float*)d_in[6];
    const float* W1   = (const float*)d_in[7];
    const float* b1   = (const float*)d_in[8];
    const float* W2   = (const float*)d_in[9];
    const float* b2   = (const float*)d_in[10];
    const float* Wc   = (const float*)d_in[11];
    const float* bc   = (const float*)d_in[12];

    void* p;
    cudaGetSymbolAddress(&p, g_social); cudaMemsetAsync(p, 0, 16 * H * sizeof(float));
    cudaGetSymbolAddress(&p, g_cnt);    cudaMemsetAsync(p, 0, sizeof(unsigned));
    cudaGetSymbolAddress(&p, g_tick);   cudaMemsetAsync(p, 0, sizeof(unsigned));
    cudaGetSymbolAddress(&p, g_fdone);  cudaMemsetAsync(p, 0, sizeof(unsigned));

    const int smemN = (H * WP + 8 * H * 4 + 16 * H) * 4;   // 78848 B
    cudaFuncSetAttribute((const void*)neighbor_kernel,
                         cudaFuncAttributeMaxDynamicSharedMemorySize, smemN);

    neighbor_kernel<<<NCTA, NTHR, smemN>>>(oth, mask, tgt, W_ih, b_ih, W_hh, b_hh);
    mlp_kernel<<<1, 256>>>(W1, b1, W2, b2, Wc, bc, (float*)d_out);
}

// round 17
// speedup vs baseline: 1.1980x; 1.0834x over previous
#include <cuda_runtime.h>
#include <cstdint>

#define NN    50000
#define OBS   15
#define H     64
#define NTHR  256
#define NCTA  296          // persistent CTAs (2 per SM)
#define WP    260          // transposed W_hh row stride (floats)

__device__ float    g_social[16 * H];
__device__ float    g_ht[H];        // final target-LSTM hidden state
__device__ float    g_hid[H];       // MLP hidden layer
__device__ unsigned g_cnt;
__device__ unsigned g_tick;
__device__ unsigned g_list[NN];     // packed: idx | (bin << 16)

// ---- activations ------------------------------------------------------------
__device__ __forceinline__ float tanh_ap(float x) {
    float y; asm("tanh.approx.f32 %0, %1;" : "=f"(y) : "f"(x)); return y;
}
__device__ __forceinline__ float sig_ap(float x) { return fmaf(0.5f, tanh_ap(0.5f * x), 0.5f); }
__device__ __forceinline__ float sigf(float x)   { return __fdividef(1.0f, 1.0f + __expf(-x)); }
__device__ __forceinline__ float tanhf_(float x) { return 2.0f * sigf(2.0f * x) - 1.0f; }

// ---------------------------------------------------------------------------
// Filter: keep neighbors with mask[14]!=0 inside the 4x4 window around
// tgt[14] — the only ones whose LSTM output is ever used.
// ---------------------------------------------------------------------------
__global__ void __launch_bounds__(256)
filter_kernel(const float* __restrict__ oth, const int* __restrict__ mask,
              const float* __restrict__ tgt)
{
    int n = blockIdx.x * blockDim.x + threadIdx.x;
    bool valid = false; int bin = 0;
    if (n < NN) {
        float2 xv = ((const float2*)oth)[(size_t)(OBS - 1) * NN + n];
        float rx = xv.x - tgt[(OBS - 1) * 2];
        float ry = xv.y - tgt[(OBS - 1) * 2 + 1];
        int m = mask[(size_t)(OBS - 1) * NN + n];
        bool within = (fabsf(rx) <= 2.0f) && (fabsf(ry) <= 2.0f);
        int cx = (int)truncf(rx) + 2;
        int cy = (int)truncf(ry) + 2;
        valid = within && cx >= 0 && cx < 4 && cy >= 0 && cy < 4 && (m != 0);
        bin = cy * 4 + cx;
    }
    unsigned ball = __ballot_sync(0xffffffffu, valid);
    int lane = threadIdx.x & 31;
    unsigned base = 0;
    if (lane == 0 && ball) base = atomicAdd(&g_cnt, (unsigned)__popc(ball));
    base = __shfl_sync(0xffffffffu, base, 0);
    if (valid) {
        int rank = __popc(ball & ((1u << lane) - 1u));
        g_list[base + rank] = (unsigned)n | ((unsigned)bin << 16);
    }
}

// ---------------------------------------------------------------------------
// Persistent neighbor LSTM (R10): warp-autonomous 4-neighbor tickets, private
// smem h buffers, no CTA barriers in mainloop. Warp 0 of CTA 0 first runs the
// 15-step target LSTM (exact activations) overlapped with ticket work.
// ---------------------------------------------------------------------------
__global__ void __launch_bounds__(NTHR)
neighbor_kernel(const float* __restrict__ oth,   // (OBS, NN, 2)
                const float* __restrict__ tgt,   // (OBS, 1, 2)
                const float* __restrict__ W_ih,  // (256, 2)
                const float* __restrict__ b_ih,  // (256)
                const float* __restrict__ W_hh,  // (256, 64)
                const float* __restrict__ b_hh)  // (256)
{
    extern __shared__ float sm[];
    float* Ws   = sm;                 // [64][WP]  Ws[k][j] = W_hh[j][k]
    float* hsA  = Ws + H * WP;        // [8][64][4] per-warp h, layout [j][i]
    float* bins = hsA + 8 * H * 4;    // [16*64]

    const int tid  = threadIdx.x;
    const int lane = tid & 31;
    const int wid  = tid >> 5;
    float* hw = hsA + wid * (H * 4);

    // stage W_hh transposed (once per CTA)
    for (int idx = tid; idx < 4 * H * H; idx += NTHR) {
        int j = idx >> 6, k = idx & 63;
        Ws[k * WP + j] = W_hh[idx];
    }
    for (int i = tid; i < 16 * H; i += NTHR) bins[i] = 0.0f;

    // per-thread gate-row constants: slot g=2q+u -> row j = 64q + 2*lane + u
    float wx0[8], wx1[8], bb[8];
    #pragma unroll
    for (int q = 0; q < 4; q++)
        #pragma unroll
        for (int u = 0; u < 2; u++) {
            int j = 64 * q + 2 * lane + u;
            wx0[q * 2 + u] = W_ih[2 * j];
            wx1[q * 2 + u] = W_ih[2 * j + 1];
            bb [q * 2 + u] = b_ih[j] + b_hh[j];
        }
    __syncthreads();   // Ws ready

    // ---- target LSTM: warp 0 of CTA 0, overlapped with ticket work --------
    if (blockIdx.x == 0 && wid == 0) {
        float bbT[8], wT0[8], wT1[8];
        #pragma unroll
        for (int q = 0; q < 4; q++)
            #pragma unroll
            for (int u = 0; u < 2; u++) {
                int j = 64 * q + lane + 32 * u;
                bbT[2 * q + u] = b_ih[j] + b_hh[j];
                wT0[2 * q + u] = W_ih[2 * j];
                wT1[2 * q + u] = W_ih[2 * j + 1];
            }
        float h0 = 0.f, h1 = 0.f, c0 = 0.f, c1 = 0.f;
        for (int t = 0; t < OBS; t++) {
            float x0 = tgt[2 * t], x1 = tgt[2 * t + 1];
            float a[8];
            #pragma unroll
            for (int g = 0; g < 8; g++)
                a[g] = fmaf(wT1[g], x1, fmaf(wT0[g], x0, bbT[g]));
            #pragma unroll 4
            for (int k = 0; k < 32; k++) {
                float hk0 = __shfl_sync(0xffffffffu, h0, k);
                float hk1 = __shfl_sync(0xffffffffu, h1, k);
                #pragma unroll
                for (int g = 0; g < 8; g++) {
                    int j = 64 * (g >> 1) + lane + 32 * (g & 1);
                    a[g] = fmaf(Ws[k * WP + j], hk0, a[g]);
                    a[g] = fmaf(Ws[(k + 32) * WP + j], hk1, a[g]);
                }
            }
            float i0 = sigf(a[0]), f0 = sigf(a[2]), g0 = tanhf_(a[4]), o0 = sigf(a[6]);
            float i1 = sigf(a[1]), f1 = sigf(a[3]), g1 = tanhf_(a[5]), o1 = sigf(a[7]);
            c0 = fmaf(f0, c0, i0 * g0);  h0 = o0 * tanhf_(c0);
            c1 = fmaf(f1, c1, i1 * g1);  h1 = o1 * tanhf_(c1);
        }
        g_ht[lane]      = h0;
        g_ht[lane + 32] = h1;
    }

    const unsigned cnt = g_cnt;

    while (true) {
        unsigned tk = 0;
        if (lane == 0) tk = atomicAdd(&g_tick, 1u);
        tk = __shfl_sync(0xffffffffu, tk, 0);
        const unsigned base = tk * 4;
        if (base >= cnt) break;          // warp-uniform

        // slots + x(0): lanes 0..3 own one neighbor each
        unsigned pk = 0xffffffffu;
        float2 xv = make_float2(0.0f, 0.0f);
        if (lane < 4 && base + lane < cnt) {
            pk = g_list[base + lane];
            xv = ((const float2*)oth)[pk & 0xffffu];
        }

        // zero this warp's h rows (2*lane, 2*lane+1)
        *(float4*)(hw + (2 * lane)     * 4) = make_float4(0.f, 0.f, 0.f, 0.f);
        *(float4*)(hw + (2 * lane + 1) * 4) = make_float4(0.f, 0.f, 0.f, 0.f);

        float creg[4][2];
        #pragma unroll
        for (int i = 0; i < 4; i++) { creg[i][0] = 0.0f; creg[i][1] = 0.0f; }

        #pragma unroll 1
        for (int t = 0; t < OBS; t++) {
            __syncwarp();   // h(t-1) writes visible

            float xi0[4], xi1[4];
            #pragma unroll
            for (int i = 0; i < 4; i++) {
                xi0[i] = __shfl_sync(0xffffffffu, xv.x, i);
                xi1[i] = __shfl_sync(0xffffffffu, xv.y, i);
            }
            // prefetch x(t+1)
            float2 xn = make_float2(0.0f, 0.0f);
            if (lane < 4 && t + 1 < OBS && pk != 0xffffffffu)
                xn = ((const float2*)oth)[(size_t)(t + 1) * NN + (pk & 0xffffu)];

            float acc[4][8];
            #pragma unroll
            for (int i = 0; i < 4; i++)
                #pragma unroll
                for (int g = 0; g < 8; g++)
                    acc[i][g] = fmaf(wx1[g], xi1[i], fmaf(wx0[g], xi0[i], bb[g]));

            const float* wcol = Ws + 2 * lane;
            #pragma unroll 8
            for (int k = 0; k < H; k++) {
                float4 h4 = *(const float4*)(hw + k * 4);   // warp-broadcast
                float2 w0 = *(const float2*)(wcol + k * WP);
                float2 w1 = *(const float2*)(wcol + k * WP + 64);
                float2 w2 = *(const float2*)(wcol + k * WP + 128);
                float2 w3 = *(const float2*)(wcol + k * WP + 192);
                float hh[4] = {h4.x, h4.y, h4.z, h4.w};
                #pragma unroll
                for (int i = 0; i < 4; i++) {
                    acc[i][0] = fmaf(w0.x, hh[i], acc[i][0]);
                    acc[i][1] = fmaf(w0.y, hh[i], acc[i][1]);
                    acc[i][2] = fmaf(w1.x, hh[i], acc[i][2]);
                    acc[i][3] = fmaf(w1.y, hh[i], acc[i][3]);
                    acc[i][4] = fmaf(w2.x, hh[i], acc[i][4]);
                    acc[i][5] = fmaf(w2.y, hh[i], acc[i][5]);
                    acc[i][6] = fmaf(w3.x, hh[i], acc[i][6]);
                    acc[i][7] = fmaf(w3.y, hh[i], acc[i][7]);
                }
            }
            __syncwarp();   // all h reads done before overwrite

            float hnew[4][2];
            #pragma unroll
            for (int i = 0; i < 4; i++)
                #pragma unroll
                for (int u = 0; u < 2; u++) {
                    float ig = sig_ap (acc[i][0 + u]);
                    float fg = sig_ap (acc[i][2 + u]);
                    float gg = tanh_ap(acc[i][4 + u]);
                    float og = sig_ap (acc[i][6 + u]);
                    float c  = fmaf(fg, creg[i][u], ig * gg);
                    creg[i][u] = c;
                    hnew[i][u] = og * tanh_ap(c);
                }
            #pragma unroll
            for (int u = 0; u < 2; u++) {
                float4 v = {hnew[0][u], hnew[1][u], hnew[2][u], hnew[3][u]};
                *(float4*)(hw + (2 * lane + u) * 4) = v;
            }
            xv = xn;
        }
        __syncwarp();

        // pooling: lane handles j = lane and j = lane+32 for the 4 neighbors
        #pragma unroll
        for (int i = 0; i < 4; i++) {
            unsigned pki = __shfl_sync(0xffffffffu, pk, i);
            if (pki != 0xffffffffu) {
                int bin = (int)(pki >> 16);
                atomicAdd(&bins[bin * H + lane],      hw[lane * 4 + i]);
                atomicAdd(&bins[bin * H + lane + 32], hw[(lane + 32) * 4 + i]);
            }
        }
    }
    __syncthreads();
    for (int i = tid; i < 16 * H; i += NTHR)
        atomicAdd(&g_social[i], bins[i]);
}

// ---------------------------------------------------------------------------
// MLP stage 1: hid[r] = relu(W1[r] . s1 + b1[r]), one CTA per row.
// 64 CTAs expose full memory parallelism for the cold 256 KB W1 read.
// ---------------------------------------------------------------------------
__global__ void __launch_bounds__(256)
mlp1_kernel(const float* __restrict__ W1, const float* __restrict__ b1)
{
    __shared__ float red[8];
    const int r   = blockIdx.x;
    const int tid = threadIdx.x;

    float p = 0.f;
    #pragma unroll
    for (int j = 0; j < 4; j++)
        p = fmaf(W1[r * 1024 + j * 256 + tid], g_social[j * 256 + tid], p);
    #pragma unroll
    for (int off = 16; off; off >>= 1) p += __shfl_xor_sync(0xffffffffu, p, off);
    if ((tid & 31) == 0) red[tid >> 5] = p;
    __syncthreads();
    if (tid < 8) {
        float v = red[tid];
        #pragma unroll
        for (int off = 4; off; off >>= 1) v += __shfl_xor_sync(0xffu, v, off);
        if (tid == 0) g_hid[r] = fmaxf(v + b1[r], 0.0f);
    }
}

// ---------------------------------------------------------------------------
// MLP stage 2: comb = g_ht + W2 @ hid + b2; out = Wc @ comb + bc.
// ---------------------------------------------------------------------------
__global__ void __launch_bounds__(256)
mlp2_kernel(const float* __restrict__ W2, const float* __restrict__ b2,
            const float* __restrict__ Wc, const float* __restrict__ bc,
            float* __restrict__ out)
{
    __shared__ float hid[H], comb[H];
    const int tid  = threadIdx.x;
    const int lane = tid & 31;
    const int wid  = tid >> 5;

    if (tid < H) hid[tid] = g_hid[tid];
    __syncthreads();

    #pragma unroll
    for (int rr = 0; rr < 8; rr++) {
        int r = wid * 8 + rr;
        float p = 0.f;
        #pragma unroll
        for (int i = 0; i < 2; i++)
            p = fmaf(W2[r * 64 + i * 32 + lane], hid[i * 32 + lane], p);
        #pragma unroll
        for (int off = 16; off; off >>= 1) p += __shfl_xor_sync(0xffffffffu, p, off);
        if (lane == 0) comb[r] = g_ht[r] + p + b2[r];
    }
    __syncthreads();

    if (wid < 2) {
        float p = 0.f;
        #pragma unroll
        for (int i = 0; i < 2; i++)
            p = fmaf(Wc[wid * 64 + i * 32 + lane], comb[i * 32 + lane], p);
        #pragma unroll
        for (int off = 16; off; off >>= 1) p += __shfl_xor_sync(0xffffffffu, p, off);
        if (lane == 0) out[wid] = p + bc[wid];
    }
}

// ---------------------------------------------------------------------------
extern "C" void kernel_launch(void* const* d_in, const int* in_sizes, int n_in,
                              void* d_out, int out_size)
{
    const float* tgt  = (const float*)d_in[0];
    const float* oth  = (const float*)d_in[1];
    const int*   mask = (const int*)  d_in[2];
    const float* W_ih = (const float*)d_in[3];
    const float* b_ih = (const float*)d_in[4];
    const float* W_hh = (const float*)d_in[5];
    const float* b_hh = (const float*)d_in[6];
    const float* W1   = (const float*)d_in[7];
    const float* b1   = (const float*)d_in[8];
    const float* W2   = (const float*)d_in[9];
    const float* b2   = (const float*)d_in[10];
    const float* Wc   = (const float*)d_in[11];
    const float* bc   = (const float*)d_in[12];

    void* p;
    cudaGetSymbolAddress(&p, g_social); cudaMemsetAsync(p, 0, 16 * H * sizeof(float));
    cudaGetSymbolAddress(&p, g_cnt);    cudaMemsetAsync(p, 0, sizeof(unsigned));
    cudaGetSymbolAddress(&p, g_tick);   cudaMemsetAsync(p, 0, sizeof(unsigned));

    const int smemN = (H * WP + 8 * H * 4 + 16 * H) * 4;   // 78848 B
    cudaFuncSetAttribute((const void*)neighbor_kernel,
                         cudaFuncAttributeMaxDynamicSharedMemorySize, smemN);

    filter_kernel<<<(NN + 255) / 256, 256>>>(oth, mask, tgt);
    neighbor_kernel<<<NCTA, NTHR, smemN>>>(oth, tgt, W_ih, b_ih, W_hh, b_hh);
    mlp1_kernel<<<H, 256>>>(W1, b1);
    mlp2_kernel<<<1, 256>>>(W2, b2, Wc, bc, (float*)d_out);
}